// round 1
// baseline (speedup 1.0000x reference)
#include <cuda_runtime.h>
#include <cuda_bf16.h>
#include <math.h>

#define BATCH 2
#define SEQ 4096
#define R (BATCH*SEQ)          // 8192 rows
#define DM 384                 // d_model
#define DI 768                 // d_inner
#define DS 16                  // d_state
#define DTR 24                 // dt_rank
#define XPN (DTR + 2*DS)       // 56
#define DFF 1536               // 4*d_model
#define LN_EPS 1e-5f

// ---------------- scratch (static device globals; no allocs) ----------------
__device__ float g_u   [R*DM];    // LN1 output
__device__ float g_xz  [R*2*DI];  // in_proj output [xi | z]
__device__ float g_xc  [R*DI];    // conv+silu output
__device__ float g_xdbl[R*XPN];   // x_proj output [dt(24) | B(16) | C(16)]
__device__ float g_dt  [R*DI];    // softplus(dt_proj)
__device__ float g_y   [R*DI];    // scan output
__device__ float g_x1  [R*DM];    // after mamba residual
__device__ float g_u2  [R*DM];    // LN2 output
__device__ float g_hf  [R*DFF];   // ffn hidden

// ---------------- LayerNorm: one block per row ----------------
__global__ void ln_kernel(const float* __restrict__ x,
                          const float* __restrict__ w,
                          const float* __restrict__ b,
                          float* __restrict__ out) {
    int row = blockIdx.x;
    const float* xr = x + row*DM;
    int tid = threadIdx.x;
    float s = 0.f, ss = 0.f;
    for (int i = tid; i < DM; i += blockDim.x) {
        float v = xr[i];
        s += v; ss += v*v;
    }
    // warp reduce
    for (int o = 16; o > 0; o >>= 1) {
        s  += __shfl_xor_sync(0xffffffffu, s, o);
        ss += __shfl_xor_sync(0xffffffffu, ss, o);
    }
    __shared__ float sh_s[4], sh_ss[4];
    int wid = tid >> 5, lid = tid & 31;
    if (lid == 0) { sh_s[wid] = s; sh_ss[wid] = ss; }
    __syncthreads();
    if (wid == 0) {
        s  = (lid < (blockDim.x>>5)) ? sh_s[lid]  : 0.f;
        ss = (lid < (blockDim.x>>5)) ? sh_ss[lid] : 0.f;
        for (int o = 2; o > 0; o >>= 1) {
            s  += __shfl_xor_sync(0xffffffffu, s, o);
            ss += __shfl_xor_sync(0xffffffffu, ss, o);
        }
        if (lid == 0) { sh_s[0] = s; sh_ss[0] = ss; }
    }
    __syncthreads();
    float mu  = sh_s[0] / DM;
    float var = sh_ss[0] / DM - mu*mu;
    float inv = rsqrtf(var + LN_EPS);
    for (int i = tid; i < DM; i += blockDim.x)
        out[row*DM + i] = (xr[i] - mu) * inv * w[i] + b[i];
}

// ---------------- generic SGEMM: C[m,n] = sum_k A[m,k]*W[n,k] (+epilogue) ---
// A: M x K row-major with stride lda; W: N x K row-major (stride K).
// act: 0 none, 1 softplus, 2 relu. order: acc + bias -> act -> + residual.
#define BM 64
#define BN 64
#define BK 16

__global__ void __launch_bounds__(256)
gemm_kernel(const float* __restrict__ A, int lda,
            const float* __restrict__ W,
            float* __restrict__ C, int ldc,
            int N, int K,
            const float* __restrict__ bias,
            const float* __restrict__ residual, int ldr,
            int act) {
    __shared__ float As[BK][BM+4];
    __shared__ float Bs[BK][BN+4];
    int bm = blockIdx.y * BM;
    int bn = blockIdx.x * BN;
    int tid = threadIdx.x;
    int tx = tid & 15;   // n group
    int ty = tid >> 4;   // m group
    float acc[4][4] = {};

    for (int k0 = 0; k0 < K; k0 += BK) {
        #pragma unroll
        for (int r = 0; r < 4; r++) {
            int mm = (tid >> 4) + r*16;
            int kk = tid & 15;
            int gk = k0 + kk;
            As[kk][mm] = (gk < K) ? A[(size_t)(bm+mm)*lda + gk] : 0.f;
        }
        #pragma unroll
        for (int r = 0; r < 4; r++) {
            int nn = (tid >> 4) + r*16;
            int kk = tid & 15;
            int gn = bn + nn, gk = k0 + kk;
            Bs[kk][nn] = (gn < N && gk < K) ? W[(size_t)gn*K + gk] : 0.f;
        }
        __syncthreads();
        #pragma unroll
        for (int kk = 0; kk < BK; kk++) {
            float a[4], bv[4];
            #pragma unroll
            for (int i = 0; i < 4; i++) a[i]  = As[kk][ty*4 + i];
            #pragma unroll
            for (int j = 0; j < 4; j++) bv[j] = Bs[kk][tx*4 + j];
            #pragma unroll
            for (int i = 0; i < 4; i++)
                #pragma unroll
                for (int j = 0; j < 4; j++)
                    acc[i][j] += a[i] * bv[j];
        }
        __syncthreads();
    }

    #pragma unroll
    for (int i = 0; i < 4; i++) {
        int gm = bm + ty*4 + i;
        #pragma unroll
        for (int j = 0; j < 4; j++) {
            int gn = bn + tx*4 + j;
            if (gn < N) {
                float v = acc[i][j];
                if (bias) v += bias[gn];
                if (act == 1) {                       // softplus
                    v = (v > 20.f) ? v : log1pf(expf(v));
                } else if (act == 2) {                // relu
                    v = fmaxf(v, 0.f);
                }
                if (residual) v += residual[(size_t)gm*ldr + gn];
                C[(size_t)gm*ldc + gn] = v;
            }
        }
    }
}

// ---------------- depthwise causal conv (k=4) + SiLU ----------------
__global__ void conv_kernel(const float* __restrict__ xz,
                            const float* __restrict__ cw,
                            const float* __restrict__ cb,
                            float* __restrict__ xc) {
    int idx = blockIdx.x * blockDim.x + threadIdx.x;
    if (idx >= R*DI) return;
    int d = idx % DI;
    int row = idx / DI;
    int s = row % SEQ;
    float acc = cb[d];
    #pragma unroll
    for (int j = 0; j < 4; j++) {
        int sp = s - 3 + j;
        if (sp >= 0)
            acc += xz[(size_t)(row - 3 + j)*(2*DI) + d] * cw[d*4 + j];
    }
    xc[idx] = acc / (1.f + expf(-acc));   // silu
}

// ---------------- selective scan: 16 lanes per (b,d) channel ----------------
__global__ void scan_kernel(const float* __restrict__ dt,
                            const float* __restrict__ xc,
                            const float* __restrict__ xdbl,
                            const float* __restrict__ A_log,
                            float* __restrict__ y) {
    int g = (blockIdx.x * blockDim.x + threadIdx.x) >> 4;   // group: b*DI+d
    int n = threadIdx.x & 15;                               // state index
    if (g >= BATCH*DI) return;
    int b = g / DI, d = g % DI;
    int bS = b * SEQ;
    float Aa = -expf(A_log[d*DS + n]);
    float h = 0.f;

    const int U = 8;
    for (int s0 = 0; s0 < SEQ; s0 += U) {
        float dtv[U], xv[U], Bv[U], Cv[U], dA[U];
        #pragma unroll
        for (int u = 0; u < U; u++) {
            int row = bS + s0 + u;
            dtv[u] = dt[(size_t)row*DI + d];
            xv[u]  = xc[(size_t)row*DI + d];
            Bv[u]  = xdbl[(size_t)row*XPN + DTR + n];
            Cv[u]  = xdbl[(size_t)row*XPN + DTR + DS + n];
            dA[u]  = expf(dtv[u] * Aa);
        }
        #pragma unroll
        for (int u = 0; u < U; u++) {
            h = dA[u]*h + dtv[u]*Bv[u]*xv[u];
            float p = h * Cv[u];
            p += __shfl_xor_sync(0xffffffffu, p, 1);
            p += __shfl_xor_sync(0xffffffffu, p, 2);
            p += __shfl_xor_sync(0xffffffffu, p, 4);
            p += __shfl_xor_sync(0xffffffffu, p, 8);
            if (n == 0) y[(size_t)(bS + s0 + u)*DI + d] = p;
        }
    }
}

// ---------------- gating: y = (y + xc*D) * silu(z) ----------------
__global__ void gate_kernel(float* __restrict__ y,
                            const float* __restrict__ xc,
                            const float* __restrict__ Dv,
                            const float* __restrict__ xz) {
    int idx = blockIdx.x * blockDim.x + threadIdx.x;
    if (idx >= R*DI) return;
    int d = idx % DI;
    int row = idx / DI;
    float z = xz[(size_t)row*(2*DI) + DI + d];
    float sz = z / (1.f + expf(-z));
    y[idx] = (y[idx] + xc[idx]*Dv[d]) * sz;
}

// ---------------- launch ----------------
extern "C" void kernel_launch(void* const* d_in, const int* in_sizes, int n_in,
                              void* d_out, int out_size) {
    const float* x         = (const float*)d_in[0];
    const float* in_proj_w = (const float*)d_in[1];
    const float* conv_w    = (const float*)d_in[2];
    const float* conv_b    = (const float*)d_in[3];
    const float* x_proj_w  = (const float*)d_in[4];
    const float* dt_proj_w = (const float*)d_in[5];
    const float* dt_proj_b = (const float*)d_in[6];
    const float* A_log     = (const float*)d_in[7];
    const float* Dp        = (const float*)d_in[8];
    const float* out_proj_w= (const float*)d_in[9];
    const float* ln1_w     = (const float*)d_in[10];
    const float* ln1_b     = (const float*)d_in[11];
    const float* ln2_w     = (const float*)d_in[12];
    const float* ln2_b     = (const float*)d_in[13];
    const float* ffn_w1    = (const float*)d_in[14];
    const float* ffn_b1    = (const float*)d_in[15];
    const float* ffn_w2    = (const float*)d_in[16];
    const float* ffn_b2    = (const float*)d_in[17];
    float* out = (float*)d_out;

    float *u, *xz, *xc, *xdbl, *dt, *y, *x1, *u2, *hf;
    cudaGetSymbolAddress((void**)&u,    g_u);
    cudaGetSymbolAddress((void**)&xz,   g_xz);
    cudaGetSymbolAddress((void**)&xc,   g_xc);
    cudaGetSymbolAddress((void**)&xdbl, g_xdbl);
    cudaGetSymbolAddress((void**)&dt,   g_dt);
    cudaGetSymbolAddress((void**)&y,    g_y);
    cudaGetSymbolAddress((void**)&x1,   g_x1);
    cudaGetSymbolAddress((void**)&u2,   g_u2);
    cudaGetSymbolAddress((void**)&hf,   g_hf);

    // 1. LN1
    ln_kernel<<<R, 128>>>(x, ln1_w, ln1_b, u);

    // 2. in_proj: (R,DM) x (2DI,DM)^T -> xz (R, 2DI)
    {
        dim3 grid((2*DI + BN - 1)/BN, R/BM);
        gemm_kernel<<<grid, 256>>>(u, DM, in_proj_w, xz, 2*DI, 2*DI, DM,
                                   nullptr, nullptr, 0, 0);
    }

    // 3. conv + silu -> xc
    {
        int total = R*DI;
        conv_kernel<<<(total + 255)/256, 256>>>(xz, conv_w, conv_b, xc);
    }

    // 4. x_proj: (R,DI) x (XPN,DI)^T -> xdbl (R, 56)
    {
        dim3 grid((XPN + BN - 1)/BN, R/BM);
        gemm_kernel<<<grid, 256>>>(xc, DI, x_proj_w, xdbl, XPN, XPN, DI,
                                   nullptr, nullptr, 0, 0);
    }

    // 5. dt_proj + softplus: (R,24) x (DI,24)^T -> dt (R, DI)
    {
        dim3 grid((DI + BN - 1)/BN, R/BM);
        gemm_kernel<<<grid, 256>>>(xdbl, XPN, dt_proj_w, dt, DI, DI, DTR,
                                   dt_proj_b, nullptr, 0, 1);
    }

    // 6. selective scan -> y
    {
        int total = BATCH*DI*16;       // 24576 threads
        scan_kernel<<<(total + 127)/128, 128>>>(dt, xc, xdbl, A_log, y);
    }

    // 7. gate
    {
        int total = R*DI;
        gate_kernel<<<(total + 255)/256, 256>>>(y, xc, Dp, xz);
    }

    // 8. out_proj + residual x -> x1
    {
        dim3 grid((DM + BN - 1)/BN, R/BM);
        gemm_kernel<<<grid, 256>>>(y, DI, out_proj_w, x1, DM, DM, DI,
                                   nullptr, x, DM, 0);
    }

    // 9. LN2
    ln_kernel<<<R, 128>>>(x1, ln2_w, ln2_b, u2);

    // 10. ffn1 + relu -> hf
    {
        dim3 grid((DFF + BN - 1)/BN, R/BM);
        gemm_kernel<<<grid, 256>>>(u2, DM, ffn_w1, hf, DFF, DFF, DM,
                                   ffn_b1, nullptr, 0, 2);
    }

    // 11. ffn2 + bias + residual x1 -> out
    {
        dim3 grid((DM + BN - 1)/BN, R/BM);
        gemm_kernel<<<grid, 256>>>(hf, DFF, ffn_w2, out, DM, DM, DFF,
                                   ffn_b2, x1, DM, 0);
    }
}

// round 2
// speedup vs baseline: 1.0590x; 1.0590x over previous
#include <cuda_runtime.h>
#include <cuda_bf16.h>
#include <math.h>

#define BATCH 2
#define SEQ 4096
#define R (BATCH*SEQ)          // 8192 rows
#define DM 384                 // d_model
#define DI 768                 // d_inner
#define DS 16                  // d_state
#define DTR 24                 // dt_rank
#define XPN (DTR + 2*DS)       // 56
#define DFF 1536               // 4*d_model
#define LN_EPS 1e-5f

// ---------------- scratch (static device globals; no allocs) ----------------
__device__ float g_u   [R*DM];    // LN1 output
__device__ float g_xz  [R*2*DI];  // in_proj output [xi | z]
__device__ float g_xc  [R*DI];    // conv+silu output
__device__ float g_xdbl[R*XPN];   // x_proj output [dt(24) | B(16) | C(16)]
__device__ float g_dt  [R*DI];    // softplus(dt_proj)
__device__ float g_y   [R*DI];    // scan output (gated)
__device__ float g_x1  [R*DM];    // after mamba residual
__device__ float g_u2  [R*DM];    // LN2 output
__device__ float g_hf  [R*DFF];   // ffn hidden

// ---------------- LayerNorm: one block per row ----------------
__global__ void ln_kernel(const float* __restrict__ x,
                          const float* __restrict__ w,
                          const float* __restrict__ b,
                          float* __restrict__ out) {
    int row = blockIdx.x;
    const float* xr = x + row*DM;
    int tid = threadIdx.x;
    float s = 0.f, ss = 0.f;
    for (int i = tid; i < DM; i += blockDim.x) {
        float v = xr[i];
        s += v; ss += v*v;
    }
    for (int o = 16; o > 0; o >>= 1) {
        s  += __shfl_xor_sync(0xffffffffu, s, o);
        ss += __shfl_xor_sync(0xffffffffu, ss, o);
    }
    __shared__ float sh_s[4], sh_ss[4];
    int wid = tid >> 5, lid = tid & 31;
    if (lid == 0) { sh_s[wid] = s; sh_ss[wid] = ss; }
    __syncthreads();
    if (wid == 0) {
        s  = (lid < (blockDim.x>>5)) ? sh_s[lid]  : 0.f;
        ss = (lid < (blockDim.x>>5)) ? sh_ss[lid] : 0.f;
        for (int o = 2; o > 0; o >>= 1) {
            s  += __shfl_xor_sync(0xffffffffu, s, o);
            ss += __shfl_xor_sync(0xffffffffu, ss, o);
        }
        if (lid == 0) { sh_s[0] = s; sh_ss[0] = ss; }
    }
    __syncthreads();
    float mu  = sh_s[0] / DM;
    float var = sh_ss[0] / DM - mu*mu;
    float inv = rsqrtf(var + LN_EPS);
    for (int i = tid; i < DM; i += blockDim.x)
        out[row*DM + i] = (xr[i] - mu) * inv * w[i] + b[i];
}

// ---------------- SGEMM 128x128x8, 8x8 micro-tile, double buffered ----------
// C[m,n] = sum_k A[m,k]*W[n,k] (+bias, act, residual)
// A: M x K row-major (lda); W: N x K row-major (stride K). M % 128 == 0.
// K % 8 == 0 and K % 4 == 0 alignment for float4; lda % 4 == 0.
#define TBM 128
#define TBN 128
#define TBK 8

__global__ void __launch_bounds__(256)
gemm128(const float* __restrict__ A, int lda,
        const float* __restrict__ W,
        float* __restrict__ C, int ldc,
        int N, int K,
        const float* __restrict__ bias,
        const float* __restrict__ residual, int ldr,
        int act) {
    __shared__ float As[2][TBK][TBM];
    __shared__ float Bs[2][TBK][TBN];

    const int bm = blockIdx.y * TBM;
    const int bn = blockIdx.x * TBN;
    const int tid = threadIdx.x;
    const int tx = tid & 15;    // 0..15 -> n fragments
    const int ty = tid >> 4;    // 0..15 -> m fragments

    const int lrow = tid >> 1;        // 0..127 (tile row for loads)
    const int lcol = (tid & 1) * 4;   // 0 or 4 (k offset)

    const int gn_load = bn + lrow;
    const bool bvalid = (gn_load < N);

    float acc[8][8];
    #pragma unroll
    for (int i = 0; i < 8; i++)
        #pragma unroll
        for (int j = 0; j < 8; j++) acc[i][j] = 0.f;

    const int nk = K / TBK;

    // prologue: load tile 0 into buffer 0
    {
        float4 va = *(const float4*)(A + (size_t)(bm + lrow)*lda + lcol);
        float4 vb = make_float4(0.f,0.f,0.f,0.f);
        if (bvalid) vb = *(const float4*)(W + (size_t)gn_load*K + lcol);
        As[0][lcol+0][lrow] = va.x; As[0][lcol+1][lrow] = va.y;
        As[0][lcol+2][lrow] = va.z; As[0][lcol+3][lrow] = va.w;
        Bs[0][lcol+0][lrow] = vb.x; Bs[0][lcol+1][lrow] = vb.y;
        Bs[0][lcol+2][lrow] = vb.z; Bs[0][lcol+3][lrow] = vb.w;
    }
    __syncthreads();

    for (int t = 0; t < nk; t++) {
        const int buf = t & 1;
        float4 va, vb;
        const bool more = (t + 1 < nk);
        if (more) {
            int k0 = (t + 1) * TBK;
            va = *(const float4*)(A + (size_t)(bm + lrow)*lda + k0 + lcol);
            vb = make_float4(0.f,0.f,0.f,0.f);
            if (bvalid) vb = *(const float4*)(W + (size_t)gn_load*K + k0 + lcol);
        }

        #pragma unroll
        for (int kk = 0; kk < TBK; kk++) {
            float a[8], b[8];
            *(float4*)(a)     = *(const float4*)&As[buf][kk][ty*4];
            *(float4*)(a + 4) = *(const float4*)&As[buf][kk][64 + ty*4];
            *(float4*)(b)     = *(const float4*)&Bs[buf][kk][tx*4];
            *(float4*)(b + 4) = *(const float4*)&Bs[buf][kk][64 + tx*4];
            #pragma unroll
            for (int i = 0; i < 8; i++)
                #pragma unroll
                for (int j = 0; j < 8; j++)
                    acc[i][j] = fmaf(a[i], b[j], acc[i][j]);
        }

        if (more) {
            const int nb = buf ^ 1;
            As[nb][lcol+0][lrow] = va.x; As[nb][lcol+1][lrow] = va.y;
            As[nb][lcol+2][lrow] = va.z; As[nb][lcol+3][lrow] = va.w;
            Bs[nb][lcol+0][lrow] = vb.x; Bs[nb][lcol+1][lrow] = vb.y;
            Bs[nb][lcol+2][lrow] = vb.z; Bs[nb][lcol+3][lrow] = vb.w;
        }
        __syncthreads();
    }

    // epilogue
    #pragma unroll
    for (int i = 0; i < 8; i++) {
        int gm = bm + ((i < 4) ? (ty*4 + i) : (64 + ty*4 + i - 4));
        #pragma unroll
        for (int j = 0; j < 8; j++) {
            int gn = bn + ((j < 4) ? (tx*4 + j) : (64 + tx*4 + j - 4));
            if (gn < N) {
                float v = acc[i][j];
                if (bias) v += bias[gn];
                if (act == 1) v = (v > 20.f) ? v : log1pf(expf(v));
                else if (act == 2) v = fmaxf(v, 0.f);
                if (residual) v += residual[(size_t)gm*ldr + gn];
                C[(size_t)gm*ldc + gn] = v;
            }
        }
    }
}

// ---------------- depthwise causal conv (k=4) + SiLU ----------------
__global__ void conv_kernel(const float* __restrict__ xz,
                            const float* __restrict__ cw,
                            const float* __restrict__ cb,
                            float* __restrict__ xc) {
    int idx = blockIdx.x * blockDim.x + threadIdx.x;
    if (idx >= R*DI) return;
    int d = idx % DI;
    int row = idx / DI;
    int s = row % SEQ;
    float acc = cb[d];
    #pragma unroll
    for (int j = 0; j < 4; j++) {
        int sp = s - 3 + j;
        if (sp >= 0)
            acc += xz[(size_t)(row - 3 + j)*(2*DI) + d] * cw[d*4 + j];
    }
    xc[idx] = acc / (1.f + expf(-acc));   // silu
}

// ---------------- selective scan (+ fused gate) -----------------------------
// 16 lanes per (b,d) channel; h in registers; shuffle reductions interleaved
// across the 8-step unroll so their latencies overlap.
// Lane 0 writes y = (sum_n h*C + xc*D) * silu(z).
__global__ void scan_kernel(const float* __restrict__ dt,
                            const float* __restrict__ xc,
                            const float* __restrict__ xdbl,
                            const float* __restrict__ A_log,
                            const float* __restrict__ Dv,
                            const float* __restrict__ xz,
                            float* __restrict__ y) {
    int g = (blockIdx.x * blockDim.x + threadIdx.x) >> 4;   // group: b*DI+d
    int n = threadIdx.x & 15;                               // state index
    if (g >= BATCH*DI) return;
    int b = g / DI, d = g % DI;
    int bS = b * SEQ;
    float Aa = -expf(A_log[d*DS + n]);
    float Dd = Dv[d];
    float h = 0.f;

    const int U = 8;
    for (int s0 = 0; s0 < SEQ; s0 += U) {
        float dtv[U], xv[U], Bv[U], Cv[U], zv[U], dA[U], p[U];
        #pragma unroll
        for (int u = 0; u < U; u++) {
            int row = bS + s0 + u;
            dtv[u] = dt[(size_t)row*DI + d];
            xv[u]  = xc[(size_t)row*DI + d];
            Bv[u]  = xdbl[(size_t)row*XPN + DTR + n];
            Cv[u]  = xdbl[(size_t)row*XPN + DTR + DS + n];
            zv[u]  = xz[(size_t)row*(2*DI) + DI + d];
            dA[u]  = expf(dtv[u] * Aa);
        }
        // sequential h recurrence; record per-lane partial products
        #pragma unroll
        for (int u = 0; u < U; u++) {
            h = fmaf(dA[u], h, dtv[u]*Bv[u]*xv[u]);
            p[u] = h * Cv[u];
        }
        // interleaved butterfly reductions (chains independent across u)
        #pragma unroll
        for (int o = 1; o < 16; o <<= 1) {
            #pragma unroll
            for (int u = 0; u < U; u++)
                p[u] += __shfl_xor_sync(0xffffffffu, p[u], o);
        }
        if (n == 0) {
            #pragma unroll
            for (int u = 0; u < U; u++) {
                float z = zv[u];
                float sz = z / (1.f + expf(-z));
                y[(size_t)(bS + s0 + u)*DI + d] = (p[u] + xv[u]*Dd) * sz;
            }
        }
    }
}

// ---------------- launch ----------------
extern "C" void kernel_launch(void* const* d_in, const int* in_sizes, int n_in,
                              void* d_out, int out_size) {
    const float* x         = (const float*)d_in[0];
    const float* in_proj_w = (const float*)d_in[1];
    const float* conv_w    = (const float*)d_in[2];
    const float* conv_b    = (const float*)d_in[3];
    const float* x_proj_w  = (const float*)d_in[4];
    const float* dt_proj_w = (const float*)d_in[5];
    const float* dt_proj_b = (const float*)d_in[6];
    const float* A_log     = (const float*)d_in[7];
    const float* Dp        = (const float*)d_in[8];
    const float* out_proj_w= (const float*)d_in[9];
    const float* ln1_w     = (const float*)d_in[10];
    const float* ln1_b     = (const float*)d_in[11];
    const float* ln2_w     = (const float*)d_in[12];
    const float* ln2_b     = (const float*)d_in[13];
    const float* ffn_w1    = (const float*)d_in[14];
    const float* ffn_b1    = (const float*)d_in[15];
    const float* ffn_w2    = (const float*)d_in[16];
    const float* ffn_b2    = (const float*)d_in[17];
    float* out = (float*)d_out;

    float *u, *xz, *xc, *xdbl, *dt, *y, *x1, *u2, *hf;
    cudaGetSymbolAddress((void**)&u,    g_u);
    cudaGetSymbolAddress((void**)&xz,   g_xz);
    cudaGetSymbolAddress((void**)&xc,   g_xc);
    cudaGetSymbolAddress((void**)&xdbl, g_xdbl);
    cudaGetSymbolAddress((void**)&dt,   g_dt);
    cudaGetSymbolAddress((void**)&y,    g_y);
    cudaGetSymbolAddress((void**)&x1,   g_x1);
    cudaGetSymbolAddress((void**)&u2,   g_u2);
    cudaGetSymbolAddress((void**)&hf,   g_hf);

    // 1. LN1
    ln_kernel<<<R, 128>>>(x, ln1_w, ln1_b, u);

    // 2. in_proj: (R,DM) x (2DI,DM)^T -> xz (R, 2DI)
    {
        dim3 grid((2*DI + TBN - 1)/TBN, R/TBM);
        gemm128<<<grid, 256>>>(u, DM, in_proj_w, xz, 2*DI, 2*DI, DM,
                               nullptr, nullptr, 0, 0);
    }

    // 3. conv + silu -> xc
    conv_kernel<<<(R*DI + 255)/256, 256>>>(xz, conv_w, conv_b, xc);

    // 4. x_proj: (R,DI) x (XPN,DI)^T -> xdbl (R, 56)
    {
        dim3 grid((XPN + TBN - 1)/TBN, R/TBM);
        gemm128<<<grid, 256>>>(xc, DI, x_proj_w, xdbl, XPN, XPN, DI,
                               nullptr, nullptr, 0, 0);
    }

    // 5. dt_proj + softplus: (R,24) x (DI,24)^T -> dt (R, DI)
    {
        dim3 grid((DI + TBN - 1)/TBN, R/TBM);
        gemm128<<<grid, 256>>>(xdbl, XPN, dt_proj_w, dt, DI, DI, DTR,
                               dt_proj_b, nullptr, 0, 1);
    }

    // 6. selective scan + gate -> y
    {
        int total = BATCH*DI*16;       // 24576 threads
        scan_kernel<<<(total + 127)/128, 128>>>(dt, xc, xdbl, A_log, Dp, xz, y);
    }

    // 7. out_proj + residual x -> x1
    {
        dim3 grid((DM + TBN - 1)/TBN, R/TBM);
        gemm128<<<grid, 256>>>(y, DI, out_proj_w, x1, DM, DM, DI,
                               nullptr, x, DM, 0);
    }

    // 8. LN2
    ln_kernel<<<R, 128>>>(x1, ln2_w, ln2_b, u2);

    // 9. ffn1 + relu -> hf
    {
        dim3 grid((DFF + TBN - 1)/TBN, R/TBM);
        gemm128<<<grid, 256>>>(u2, DM, ffn_w1, hf, DFF, DFF, DM,
                               ffn_b1, nullptr, 0, 2);
    }

    // 10. ffn2 + bias + residual x1 -> out
    {
        dim3 grid((DM + TBN - 1)/TBN, R/TBM);
        gemm128<<<grid, 256>>>(hf, DFF, ffn_w2, out, DM, DM, DFF,
                               ffn_b2, x1, DM, 0);
    }
}

// round 3
// speedup vs baseline: 1.5002x; 1.4165x over previous
#include <cuda_runtime.h>
#include <cuda_bf16.h>
#include <math.h>

#define BATCH 2
#define SEQ 4096
#define R (BATCH*SEQ)          // 8192 rows
#define DM 384                 // d_model
#define DI 768                 // d_inner
#define DS 16                  // d_state
#define DTR 24                 // dt_rank
#define XPN (DTR + 2*DS)       // 56
#define DFF 1536               // 4*d_model
#define LN_EPS 1e-5f

// ---------------- scratch (static device globals; no allocs) ----------------
__device__ float g_u   [R*DM];    // LN1 output
__device__ float g_xz  [R*2*DI];  // in_proj output [xi | z]
__device__ float g_xc  [R*DI];    // conv+silu output
__device__ float g_xdbl[R*XPN];   // x_proj output [dt(24) | B(16) | C(16)]
__device__ float g_dt  [R*DI];    // softplus(dt_proj)
__device__ float g_y   [R*DI];    // scan output (gated)
__device__ float g_x1  [R*DM];    // after mamba residual
__device__ float g_u2  [R*DM];    // LN2 output
__device__ float g_hf  [R*DFF];   // ffn hidden

// ---------------- LayerNorm ----------------
__global__ void ln_kernel(const float* __restrict__ x,
                          const float* __restrict__ w,
                          const float* __restrict__ b,
                          float* __restrict__ out) {
    int row = blockIdx.x;
    const float* xr = x + row*DM;
    int tid = threadIdx.x;
    float s = 0.f, ss = 0.f;
    for (int i = tid; i < DM; i += blockDim.x) {
        float v = xr[i];
        s += v; ss += v*v;
    }
    for (int o = 16; o > 0; o >>= 1) {
        s  += __shfl_xor_sync(0xffffffffu, s, o);
        ss += __shfl_xor_sync(0xffffffffu, ss, o);
    }
    __shared__ float sh_s[4], sh_ss[4];
    int wid = tid >> 5, lid = tid & 31;
    if (lid == 0) { sh_s[wid] = s; sh_ss[wid] = ss; }
    __syncthreads();
    if (wid == 0) {
        s  = (lid < (blockDim.x>>5)) ? sh_s[lid]  : 0.f;
        ss = (lid < (blockDim.x>>5)) ? sh_ss[lid] : 0.f;
        for (int o = 2; o > 0; o >>= 1) {
            s  += __shfl_xor_sync(0xffffffffu, s, o);
            ss += __shfl_xor_sync(0xffffffffu, ss, o);
        }
        if (lid == 0) { sh_s[0] = s; sh_ss[0] = ss; }
    }
    __syncthreads();
    float mu  = sh_s[0] / DM;
    float var = sh_ss[0] / DM - mu*mu;
    float inv = rsqrtf(var + LN_EPS);
    for (int i = tid; i < DM; i += blockDim.x)
        out[row*DM + i] = (xr[i] - mu) * inv * w[i] + b[i];
}

// ================= TF32 tensor-core GEMM =================
// C[m,n] = sum_k A[m,k] * W[n,k]  (+bias, act, +residual)
// A: M x K row-major (lda, K%4==0). W: N x K row-major. M%128==0. N,K arbitrary
// (K%4==0). Tiles 128x128x16, 256 threads, warp tile 64x32 via m16n8k8 tf32.
// Smem rows padded to stride 20 -> all fragment LDS patterns conflict-free.

#define SA 20

__device__ __forceinline__ unsigned f2tf(float f) {
    unsigned u;
    asm("cvt.rna.tf32.f32 %0, %1;" : "=r"(u) : "f"(f));
    return u;
}

__device__ __forceinline__ void mma_tf32(float* c, const unsigned* a, const unsigned* b) {
    asm volatile(
        "mma.sync.aligned.m16n8k8.row.col.f32.tf32.tf32.f32 "
        "{%0,%1,%2,%3}, {%4,%5,%6,%7}, {%8,%9}, {%0,%1,%2,%3};"
        : "+f"(c[0]), "+f"(c[1]), "+f"(c[2]), "+f"(c[3])
        : "r"(a[0]), "r"(a[1]), "r"(a[2]), "r"(a[3]), "r"(b[0]), "r"(b[1]));
}

__global__ void __launch_bounds__(256)
gemm_tf32(const float* __restrict__ A, int lda,
          const float* __restrict__ W,
          float* __restrict__ C, int ldc,
          int N, int K,
          const float* __restrict__ bias,
          const float* __restrict__ residual, int ldr,
          int act) {
    __shared__ unsigned As[2][128][SA];
    __shared__ unsigned Bs[2][128][SA];

    const int bm = blockIdx.y * 128;
    const int bn = blockIdx.x * 128;
    const int tid = threadIdx.x;
    const int wid = tid >> 5;
    const int lane = tid & 31;
    const int g   = lane >> 2;   // groupID
    const int tig = lane & 3;    // thread-in-group
    const int warp_m = wid & 1;          // 0..1 -> 64 rows
    const int warp_n = wid >> 1;         // 0..3 -> 32 cols

    // loader mapping: 128 rows x 16 k per operand, 2 rows per thread
    const int lrow = tid >> 2;          // 0..63
    const int lkq  = (tid & 3) * 4;     // 0,4,8,12

    float acc[4][4][4];
    #pragma unroll
    for (int i = 0; i < 4; i++)
        #pragma unroll
        for (int j = 0; j < 4; j++)
            #pragma unroll
            for (int q = 0; q < 4; q++) acc[i][j][q] = 0.f;

    const int nk = (K + 15) / 16;

    // ---- tile loader (guarded, tf32-converted) ----
    auto ldA = [&](int m, int k0) -> float4 {
        if (k0 + lkq <= K - 4)
            return *(const float4*)(A + (size_t)(bm + m)*lda + k0 + lkq);
        return make_float4(0.f,0.f,0.f,0.f);
    };
    auto ldW = [&](int n, int k0) -> float4 {
        if (bn + n < N && k0 + lkq <= K - 4)
            return *(const float4*)(W + (size_t)(bn + n)*K + k0 + lkq);
        return make_float4(0.f,0.f,0.f,0.f);
    };
    auto stTile = [&](int buf, float4 a0, float4 a1, float4 b0, float4 b1) {
        uint4 v;
        v.x=f2tf(a0.x); v.y=f2tf(a0.y); v.z=f2tf(a0.z); v.w=f2tf(a0.w);
        *(uint4*)&As[buf][lrow][lkq] = v;
        v.x=f2tf(a1.x); v.y=f2tf(a1.y); v.z=f2tf(a1.z); v.w=f2tf(a1.w);
        *(uint4*)&As[buf][lrow+64][lkq] = v;
        v.x=f2tf(b0.x); v.y=f2tf(b0.y); v.z=f2tf(b0.z); v.w=f2tf(b0.w);
        *(uint4*)&Bs[buf][lrow][lkq] = v;
        v.x=f2tf(b1.x); v.y=f2tf(b1.y); v.z=f2tf(b1.z); v.w=f2tf(b1.w);
        *(uint4*)&Bs[buf][lrow+64][lkq] = v;
    };

    // prologue
    stTile(0, ldA(lrow,0), ldA(lrow+64,0), ldW(lrow,0), ldW(lrow+64,0));
    __syncthreads();

    for (int t = 0; t < nk; t++) {
        const int buf = t & 1;
        float4 pa0, pa1, pb0, pb1;
        const bool more = (t + 1 < nk);
        if (more) {
            int k0 = (t+1)*16;
            pa0 = ldA(lrow, k0); pa1 = ldA(lrow+64, k0);
            pb0 = ldW(lrow, k0); pb1 = ldW(lrow+64, k0);
        }

        #pragma unroll
        for (int s = 0; s < 2; s++) {
            const int ks = s * 8;
            unsigned af[4][4], bf[4][2];
            #pragma unroll
            for (int i = 0; i < 4; i++) {
                int m0 = warp_m*64 + i*16;
                af[i][0] = As[buf][m0 + g    ][ks + tig];
                af[i][1] = As[buf][m0 + g + 8][ks + tig];
                af[i][2] = As[buf][m0 + g    ][ks + tig + 4];
                af[i][3] = As[buf][m0 + g + 8][ks + tig + 4];
            }
            #pragma unroll
            for (int j = 0; j < 4; j++) {
                int n0 = warp_n*32 + j*8;
                bf[j][0] = Bs[buf][n0 + g][ks + tig];
                bf[j][1] = Bs[buf][n0 + g][ks + tig + 4];
            }
            #pragma unroll
            for (int i = 0; i < 4; i++)
                #pragma unroll
                for (int j = 0; j < 4; j++)
                    mma_tf32(acc[i][j], af[i], bf[j]);
        }

        if (more) stTile(buf ^ 1, pa0, pa1, pb0, pb1);
        __syncthreads();
    }

    // ---- epilogue ----
    #pragma unroll
    for (int i = 0; i < 4; i++) {
        #pragma unroll
        for (int j = 0; j < 4; j++) {
            int nc = bn + warp_n*32 + j*8 + 2*tig;
            #pragma unroll
            for (int half = 0; half < 2; half++) {
                int gm = bm + warp_m*64 + i*16 + g + half*8;
                float v0 = acc[i][j][half*2 + 0];
                float v1 = acc[i][j][half*2 + 1];
                #pragma unroll
                for (int e = 0; e < 2; e++) {
                    int gn = nc + e;
                    if (gn < N) {
                        float v = e ? v1 : v0;
                        if (bias) v += bias[gn];
                        if (act == 1) v = (v > 20.f) ? v : log1pf(expf(v));
                        else if (act == 2) v = fmaxf(v, 0.f);
                        if (residual) v += residual[(size_t)gm*ldr + gn];
                        C[(size_t)gm*ldc + gn] = v;
                    }
                }
            }
        }
    }
}

// ---------------- depthwise causal conv (k=4) + SiLU ----------------
__global__ void conv_kernel(const float* __restrict__ xz,
                            const float* __restrict__ cw,
                            const float* __restrict__ cb,
                            float* __restrict__ xc) {
    int idx = blockIdx.x * blockDim.x + threadIdx.x;
    if (idx >= R*DI) return;
    int d = idx % DI;
    int row = idx / DI;
    int s = row % SEQ;
    float acc = cb[d];
    #pragma unroll
    for (int j = 0; j < 4; j++) {
        int sp = s - 3 + j;
        if (sp >= 0)
            acc += xz[(size_t)(row - 3 + j)*(2*DI) + d] * cw[d*4 + j];
    }
    xc[idx] = acc / (1.f + expf(-acc));   // silu
}

// ---------------- selective scan (+ fused gate) -----------------------------
__global__ void scan_kernel(const float* __restrict__ dt,
                            const float* __restrict__ xc,
                            const float* __restrict__ xdbl,
                            const float* __restrict__ A_log,
                            const float* __restrict__ Dv,
                            const float* __restrict__ xz,
                            float* __restrict__ y) {
    int g = (blockIdx.x * blockDim.x + threadIdx.x) >> 4;   // group: b*DI+d
    int n = threadIdx.x & 15;                               // state index
    if (g >= BATCH*DI) return;
    int b = g / DI, d = g % DI;
    int bS = b * SEQ;
    float Aa = -expf(A_log[d*DS + n]);
    float Dd = Dv[d];
    float h = 0.f;

    const int U = 8;
    for (int s0 = 0; s0 < SEQ; s0 += U) {
        float dtv[U], xv[U], Bv[U], Cv[U], zv[U], dA[U], p[U];
        #pragma unroll
        for (int u = 0; u < U; u++) {
            int row = bS + s0 + u;
            dtv[u] = dt[(size_t)row*DI + d];
            xv[u]  = xc[(size_t)row*DI + d];
            Bv[u]  = xdbl[(size_t)row*XPN + DTR + n];
            Cv[u]  = xdbl[(size_t)row*XPN + DTR + DS + n];
            zv[u]  = xz[(size_t)row*(2*DI) + DI + d];
            dA[u]  = expf(dtv[u] * Aa);
        }
        #pragma unroll
        for (int u = 0; u < U; u++) {
            h = fmaf(dA[u], h, dtv[u]*Bv[u]*xv[u]);
            p[u] = h * Cv[u];
        }
        #pragma unroll
        for (int o = 1; o < 16; o <<= 1) {
            #pragma unroll
            for (int u = 0; u < U; u++)
                p[u] += __shfl_xor_sync(0xffffffffu, p[u], o);
        }
        if (n == 0) {
            #pragma unroll
            for (int u = 0; u < U; u++) {
                float z = zv[u];
                float sz = z / (1.f + expf(-z));
                y[(size_t)(bS + s0 + u)*DI + d] = (p[u] + xv[u]*Dd) * sz;
            }
        }
    }
}

// ---------------- launch ----------------
extern "C" void kernel_launch(void* const* d_in, const int* in_sizes, int n_in,
                              void* d_out, int out_size) {
    const float* x         = (const float*)d_in[0];
    const float* in_proj_w = (const float*)d_in[1];
    const float* conv_w    = (const float*)d_in[2];
    const float* conv_b    = (const float*)d_in[3];
    const float* x_proj_w  = (const float*)d_in[4];
    const float* dt_proj_w = (const float*)d_in[5];
    const float* dt_proj_b = (const float*)d_in[6];
    const float* A_log     = (const float*)d_in[7];
    const float* Dp        = (const float*)d_in[8];
    const float* out_proj_w= (const float*)d_in[9];
    const float* ln1_w     = (const float*)d_in[10];
    const float* ln1_b     = (const float*)d_in[11];
    const float* ln2_w     = (const float*)d_in[12];
    const float* ln2_b     = (const float*)d_in[13];
    const float* ffn_w1    = (const float*)d_in[14];
    const float* ffn_b1    = (const float*)d_in[15];
    const float* ffn_w2    = (const float*)d_in[16];
    const float* ffn_b2    = (const float*)d_in[17];
    float* out = (float*)d_out;

    float *u, *xz, *xc, *xdbl, *dt, *y, *x1, *u2, *hf;
    cudaGetSymbolAddress((void**)&u,    g_u);
    cudaGetSymbolAddress((void**)&xz,   g_xz);
    cudaGetSymbolAddress((void**)&xc,   g_xc);
    cudaGetSymbolAddress((void**)&xdbl, g_xdbl);
    cudaGetSymbolAddress((void**)&dt,   g_dt);
    cudaGetSymbolAddress((void**)&y,    g_y);
    cudaGetSymbolAddress((void**)&x1,   g_x1);
    cudaGetSymbolAddress((void**)&u2,   g_u2);
    cudaGetSymbolAddress((void**)&hf,   g_hf);

    // 1. LN1
    ln_kernel<<<R, 128>>>(x, ln1_w, ln1_b, u);

    // 2. in_proj
    {
        dim3 grid((2*DI + 127)/128, R/128);
        gemm_tf32<<<grid, 256>>>(u, DM, in_proj_w, xz, 2*DI, 2*DI, DM,
                                 nullptr, nullptr, 0, 0);
    }

    // 3. conv + silu
    conv_kernel<<<(R*DI + 255)/256, 256>>>(xz, conv_w, conv_b, xc);

    // 4. x_proj
    {
        dim3 grid((XPN + 127)/128, R/128);
        gemm_tf32<<<grid, 256>>>(xc, DI, x_proj_w, xdbl, XPN, XPN, DI,
                                 nullptr, nullptr, 0, 0);
    }

    // 5. dt_proj + softplus
    {
        dim3 grid((DI + 127)/128, R/128);
        gemm_tf32<<<grid, 256>>>(xdbl, XPN, dt_proj_w, dt, DI, DI, DTR,
                                 dt_proj_b, nullptr, 0, 1);
    }

    // 6. selective scan + gate
    {
        int total = BATCH*DI*16;
        scan_kernel<<<(total + 127)/128, 128>>>(dt, xc, xdbl, A_log, Dp, xz, y);
    }

    // 7. out_proj + residual x
    {
        dim3 grid((DM + 127)/128, R/128);
        gemm_tf32<<<grid, 256>>>(y, DI, out_proj_w, x1, DM, DM, DI,
                                 nullptr, x, DM, 0);
    }

    // 8. LN2
    ln_kernel<<<R, 128>>>(x1, ln2_w, ln2_b, u2);

    // 9. ffn1 + relu
    {
        dim3 grid((DFF + 127)/128, R/128);
        gemm_tf32<<<grid, 256>>>(u2, DM, ffn_w1, hf, DFF, DFF, DM,
                                 ffn_b1, nullptr, 0, 2);
    }

    // 10. ffn2 + bias + residual x1
    {
        dim3 grid((DM + 127)/128, R/128);
        gemm_tf32<<<grid, 256>>>(hf, DFF, ffn_w2, out, DM, DM, DFF,
                                 ffn_b2, x1, DM, 0);
    }
}

// round 4
// speedup vs baseline: 1.5038x; 1.0024x over previous
#include <cuda_runtime.h>
#include <cuda_bf16.h>
#include <math.h>

#define BATCH 2
#define SEQ 4096
#define R (BATCH*SEQ)          // 8192 rows
#define DM 384                 // d_model
#define DI 768                 // d_inner
#define DS 16                  // d_state
#define DTR 24                 // dt_rank
#define XPN (DTR + 2*DS)       // 56
#define DFF 1536               // 4*d_model
#define LN_EPS 1e-5f

// ---------------- scratch (static device globals; no allocs) ----------------
__device__ float g_u   [R*DM];
__device__ float g_xz  [R*2*DI];
__device__ float g_xc  [R*DI];
__device__ float g_xdbl[R*XPN];
__device__ float g_dt  [R*DI];
__device__ float g_y   [R*DI];
__device__ float g_x1  [R*DM];
__device__ float g_u2  [R*DM];
__device__ float g_hf  [R*DFF];

// ---------------- LayerNorm ----------------
__global__ void ln_kernel(const float* __restrict__ x,
                          const float* __restrict__ w,
                          const float* __restrict__ b,
                          float* __restrict__ out) {
    int row = blockIdx.x;
    const float* xr = x + row*DM;
    int tid = threadIdx.x;
    float s = 0.f, ss = 0.f;
    for (int i = tid; i < DM; i += blockDim.x) {
        float v = xr[i];
        s += v; ss += v*v;
    }
    for (int o = 16; o > 0; o >>= 1) {
        s  += __shfl_xor_sync(0xffffffffu, s, o);
        ss += __shfl_xor_sync(0xffffffffu, ss, o);
    }
    __shared__ float sh_s[4], sh_ss[4];
    int wid = tid >> 5, lid = tid & 31;
    if (lid == 0) { sh_s[wid] = s; sh_ss[wid] = ss; }
    __syncthreads();
    if (wid == 0) {
        s  = (lid < (blockDim.x>>5)) ? sh_s[lid]  : 0.f;
        ss = (lid < (blockDim.x>>5)) ? sh_ss[lid] : 0.f;
        for (int o = 2; o > 0; o >>= 1) {
            s  += __shfl_xor_sync(0xffffffffu, s, o);
            ss += __shfl_xor_sync(0xffffffffu, ss, o);
        }
        if (lid == 0) { sh_s[0] = s; sh_ss[0] = ss; }
    }
    __syncthreads();
    float mu  = sh_s[0] / DM;
    float var = sh_ss[0] / DM - mu*mu;
    float inv = rsqrtf(var + LN_EPS);
    for (int i = tid; i < DM; i += blockDim.x)
        out[row*DM + i] = (xr[i] - mu) * inv * w[i] + b[i];
}

// ================= TF32 tensor-core GEMM (templated tile) =================
// C[m,n] = sum_k A[m,k] * W[n,k]  (+bias, act, +residual)
// Warp layout: 2 warps in M x 4 warps in N (256 threads).
// Template: MF = m16-fragments per warp, NF = n8-fragments per warp.
//   Block tile = (2*MF*16) x (4*NF*8).  <4,4> -> 128x128,  <2,2> -> 64x64.
// Smem rows stride SA=20 -> conflict-free for all fragment LDS patterns.

#define SA 20

__device__ __forceinline__ unsigned f2tf(float f) {
    unsigned u;
    asm("cvt.rna.tf32.f32 %0, %1;" : "=r"(u) : "f"(f));
    return u;
}

__device__ __forceinline__ void mma_tf32(float* c, const unsigned* a, const unsigned* b) {
    asm volatile(
        "mma.sync.aligned.m16n8k8.row.col.f32.tf32.tf32.f32 "
        "{%0,%1,%2,%3}, {%4,%5,%6,%7}, {%8,%9}, {%0,%1,%2,%3};"
        : "+f"(c[0]), "+f"(c[1]), "+f"(c[2]), "+f"(c[3])
        : "r"(a[0]), "r"(a[1]), "r"(a[2]), "r"(a[3]), "r"(b[0]), "r"(b[1]));
}

template<int MF, int NF>
__global__ void __launch_bounds__(256)
gemm_tf32(const float* __restrict__ A, int lda,
          const float* __restrict__ W,
          float* __restrict__ C, int ldc,
          int N, int K,
          const float* __restrict__ bias,
          const float* __restrict__ residual, int ldr,
          int act) {
    constexpr int BM = 2*MF*16;
    constexpr int BN = 4*NF*8;
    constexpr int AR = BM/64;    // float4 loads per thread for A tile
    constexpr int BR = BN/64;

    __shared__ unsigned As[2][BM][SA];
    __shared__ unsigned Bs[2][BN][SA];

    const int bm = blockIdx.y * BM;
    const int bn = blockIdx.x * BN;
    const int tid = threadIdx.x;
    const int wid = tid >> 5;
    const int lane = tid & 31;
    const int g   = lane >> 2;   // groupID
    const int tig = lane & 3;    // thread-in-group
    const int warp_m = wid & 1;
    const int warp_n = wid >> 1;

    const int lrow = tid >> 2;        // 0..63
    const int lkq  = (tid & 3) * 4;   // 0,4,8,12

    float acc[MF][NF][4];
    #pragma unroll
    for (int i = 0; i < MF; i++)
        #pragma unroll
        for (int j = 0; j < NF; j++)
            #pragma unroll
            for (int q = 0; q < 4; q++) acc[i][j][q] = 0.f;

    const int nk = (K + 15) / 16;

    auto ldA = [&](int m, int k0) -> float4 {
        if (k0 + lkq <= K - 4)
            return *(const float4*)(A + (size_t)(bm + m)*lda + k0 + lkq);
        return make_float4(0.f,0.f,0.f,0.f);
    };
    auto ldW = [&](int n, int k0) -> float4 {
        if (bn + n < N && k0 + lkq <= K - 4)
            return *(const float4*)(W + (size_t)(bn + n)*K + k0 + lkq);
        return make_float4(0.f,0.f,0.f,0.f);
    };
    auto stTile = [&](int buf, const float4* a, const float4* b) {
        #pragma unroll
        for (int r = 0; r < AR; r++) {
            uint4 v;
            v.x=f2tf(a[r].x); v.y=f2tf(a[r].y); v.z=f2tf(a[r].z); v.w=f2tf(a[r].w);
            *(uint4*)&As[buf][lrow + r*64][lkq] = v;
        }
        #pragma unroll
        for (int r = 0; r < BR; r++) {
            uint4 v;
            v.x=f2tf(b[r].x); v.y=f2tf(b[r].y); v.z=f2tf(b[r].z); v.w=f2tf(b[r].w);
            *(uint4*)&Bs[buf][lrow + r*64][lkq] = v;
        }
    };

    // prologue
    {
        float4 a[AR], b[BR];
        #pragma unroll
        for (int r = 0; r < AR; r++) a[r] = ldA(lrow + r*64, 0);
        #pragma unroll
        for (int r = 0; r < BR; r++) b[r] = ldW(lrow + r*64, 0);
        stTile(0, a, b);
    }
    __syncthreads();

    for (int t = 0; t < nk; t++) {
        const int buf = t & 1;
        float4 pa[AR], pb[BR];
        const bool more = (t + 1 < nk);
        if (more) {
            int k0 = (t+1)*16;
            #pragma unroll
            for (int r = 0; r < AR; r++) pa[r] = ldA(lrow + r*64, k0);
            #pragma unroll
            for (int r = 0; r < BR; r++) pb[r] = ldW(lrow + r*64, k0);
        }

        #pragma unroll
        for (int s = 0; s < 2; s++) {
            const int ks = s * 8;
            unsigned af[MF][4], bf[NF][2];
            #pragma unroll
            for (int i = 0; i < MF; i++) {
                int m0 = warp_m*(MF*16) + i*16;
                af[i][0] = As[buf][m0 + g    ][ks + tig];
                af[i][1] = As[buf][m0 + g + 8][ks + tig];
                af[i][2] = As[buf][m0 + g    ][ks + tig + 4];
                af[i][3] = As[buf][m0 + g + 8][ks + tig + 4];
            }
            #pragma unroll
            for (int j = 0; j < NF; j++) {
                int n0 = warp_n*(NF*8) + j*8;
                bf[j][0] = Bs[buf][n0 + g][ks + tig];
                bf[j][1] = Bs[buf][n0 + g][ks + tig + 4];
            }
            #pragma unroll
            for (int i = 0; i < MF; i++)
                #pragma unroll
                for (int j = 0; j < NF; j++)
                    mma_tf32(acc[i][j], af[i], bf[j]);
        }

        if (more) stTile(buf ^ 1, pa, pb);
        __syncthreads();
    }

    // ---- epilogue ----
    #pragma unroll
    for (int i = 0; i < MF; i++) {
        #pragma unroll
        for (int j = 0; j < NF; j++) {
            int nc = bn + warp_n*(NF*8) + j*8 + 2*tig;
            #pragma unroll
            for (int half = 0; half < 2; half++) {
                int gm = bm + warp_m*(MF*16) + i*16 + g + half*8;
                #pragma unroll
                for (int e = 0; e < 2; e++) {
                    int gn = nc + e;
                    if (gn < N) {
                        float v = acc[i][j][half*2 + e];
                        if (bias) v += bias[gn];
                        if (act == 1) v = (v > 20.f) ? v : log1pf(expf(v));
                        else if (act == 2) v = fmaxf(v, 0.f);
                        if (residual) v += residual[(size_t)gm*ldr + gn];
                        C[(size_t)gm*ldc + gn] = v;
                    }
                }
            }
        }
    }
}

// ---------------- depthwise causal conv (k=4) + SiLU ----------------
__global__ void conv_kernel(const float* __restrict__ xz,
                            const float* __restrict__ cw,
                            const float* __restrict__ cb,
                            float* __restrict__ xc) {
    int idx = blockIdx.x * blockDim.x + threadIdx.x;
    if (idx >= R*DI) return;
    int d = idx % DI;
    int row = idx / DI;
    int s = row % SEQ;
    float acc = cb[d];
    #pragma unroll
    for (int j = 0; j < 4; j++) {
        int sp = s - 3 + j;
        if (sp >= 0)
            acc += xz[(size_t)(row - 3 + j)*(2*DI) + d] * cw[d*4 + j];
    }
    xc[idx] = acc / (1.f + expf(-acc));
}

// ---------------- selective scan (+ fused gate) -----------------------------
__global__ void scan_kernel(const float* __restrict__ dt,
                            const float* __restrict__ xc,
                            const float* __restrict__ xdbl,
                            const float* __restrict__ A_log,
                            const float* __restrict__ Dv,
                            const float* __restrict__ xz,
                            float* __restrict__ y) {
    int g = (blockIdx.x * blockDim.x + threadIdx.x) >> 4;
    int n = threadIdx.x & 15;
    if (g >= BATCH*DI) return;
    int b = g / DI, d = g % DI;
    int bS = b * SEQ;
    float Aa = -expf(A_log[d*DS + n]);
    float Dd = Dv[d];
    float h = 0.f;

    const int U = 8;
    for (int s0 = 0; s0 < SEQ; s0 += U) {
        float dtv[U], xv[U], Bv[U], Cv[U], zv[U], dA[U], p[U];
        #pragma unroll
        for (int u = 0; u < U; u++) {
            int row = bS + s0 + u;
            dtv[u] = dt[(size_t)row*DI + d];
            xv[u]  = xc[(size_t)row*DI + d];
            Bv[u]  = xdbl[(size_t)row*XPN + DTR + n];
            Cv[u]  = xdbl[(size_t)row*XPN + DTR + DS + n];
            zv[u]  = xz[(size_t)row*(2*DI) + DI + d];
            dA[u]  = expf(dtv[u] * Aa);
        }
        #pragma unroll
        for (int u = 0; u < U; u++) {
            h = fmaf(dA[u], h, dtv[u]*Bv[u]*xv[u]);
            p[u] = h * Cv[u];
        }
        #pragma unroll
        for (int o = 1; o < 16; o <<= 1) {
            #pragma unroll
            for (int u = 0; u < U; u++)
                p[u] += __shfl_xor_sync(0xffffffffu, p[u], o);
        }
        if (n == 0) {
            #pragma unroll
            for (int u = 0; u < U; u++) {
                float z = zv[u];
                float sz = z / (1.f + expf(-z));
                y[(size_t)(bS + s0 + u)*DI + d] = (p[u] + xv[u]*Dd) * sz;
            }
        }
    }
}

// ---------------- launch ----------------
extern "C" void kernel_launch(void* const* d_in, const int* in_sizes, int n_in,
                              void* d_out, int out_size) {
    const float* x         = (const float*)d_in[0];
    const float* in_proj_w = (const float*)d_in[1];
    const float* conv_w    = (const float*)d_in[2];
    const float* conv_b    = (const float*)d_in[3];
    const float* x_proj_w  = (const float*)d_in[4];
    const float* dt_proj_w = (const float*)d_in[5];
    const float* dt_proj_b = (const float*)d_in[6];
    const float* A_log     = (const float*)d_in[7];
    const float* Dp        = (const float*)d_in[8];
    const float* out_proj_w= (const float*)d_in[9];
    const float* ln1_w     = (const float*)d_in[10];
    const float* ln1_b     = (const float*)d_in[11];
    const float* ln2_w     = (const float*)d_in[12];
    const float* ln2_b     = (const float*)d_in[13];
    const float* ffn_w1    = (const float*)d_in[14];
    const float* ffn_b1    = (const float*)d_in[15];
    const float* ffn_w2    = (const float*)d_in[16];
    const float* ffn_b2    = (const float*)d_in[17];
    float* out = (float*)d_out;

    float *u, *xz, *xc, *xdbl, *dt, *y, *x1, *u2, *hf;
    cudaGetSymbolAddress((void**)&u,    g_u);
    cudaGetSymbolAddress((void**)&xz,   g_xz);
    cudaGetSymbolAddress((void**)&xc,   g_xc);
    cudaGetSymbolAddress((void**)&xdbl, g_xdbl);
    cudaGetSymbolAddress((void**)&dt,   g_dt);
    cudaGetSymbolAddress((void**)&y,    g_y);
    cudaGetSymbolAddress((void**)&x1,   g_x1);
    cudaGetSymbolAddress((void**)&u2,   g_u2);
    cudaGetSymbolAddress((void**)&hf,   g_hf);

    // 1. LN1
    ln_kernel<<<R, 128>>>(x, ln1_w, ln1_b, u);

    // 2. in_proj (wide): 128x128 tiles
    gemm_tf32<4,4><<<dim3((2*DI+127)/128, R/128), 256>>>(
        u, DM, in_proj_w, xz, 2*DI, 2*DI, DM, nullptr, nullptr, 0, 0);

    // 3. conv + silu
    conv_kernel<<<(R*DI + 255)/256, 256>>>(xz, conv_w, conv_b, xc);

    // 4. x_proj (narrow N=56): 64x64 tiles
    gemm_tf32<2,2><<<dim3((XPN+63)/64, R/64), 256>>>(
        xc, DI, x_proj_w, xdbl, XPN, XPN, DI, nullptr, nullptr, 0, 0);

    // 5. dt_proj + softplus (K=24): 64x64 tiles
    gemm_tf32<2,2><<<dim3((DI+63)/64, R/64), 256>>>(
        xdbl, XPN, dt_proj_w, dt, DI, DI, DTR, dt_proj_b, nullptr, 0, 1);

    // 6. selective scan + gate
    {
        int total = BATCH*DI*16;
        scan_kernel<<<(total + 127)/128, 128>>>(dt, xc, xdbl, A_log, Dp, xz, y);
    }

    // 7. out_proj + residual (N=384): 64x64 tiles
    gemm_tf32<2,2><<<dim3((DM+63)/64, R/64), 256>>>(
        y, DI, out_proj_w, x1, DM, DM, DI, nullptr, x, DM, 0);

    // 8. LN2
    ln_kernel<<<R, 128>>>(x1, ln2_w, ln2_b, u2);

    // 9. ffn1 + relu (wide): 128x128 tiles
    gemm_tf32<4,4><<<dim3((DFF+127)/128, R/128), 256>>>(
        u2, DM, ffn_w1, hf, DFF, DFF, DM, ffn_b1, nullptr, 0, 2);

    // 10. ffn2 + bias + residual (N=384, K=1536): 64x64 tiles
    gemm_tf32<2,2><<<dim3((DM+63)/64, R/64), 256>>>(
        hf, DFF, ffn_w2, out, DM, DM, DFF, ffn_b2, x1, DM, 0);
}